// round 14
// baseline (speedup 1.0000x reference)
#include <cuda_runtime.h>

#define LATENT  10
#define MAXLEN  80
#define BATCH   512
#define NSTEPS  100
#define HID     64
#define DTC     0.01f

typedef unsigned long long u64;
typedef unsigned int u32;

// ---------------- packed f32x2 helpers (sm_100+) ----------------
__device__ __forceinline__ u64 pk(float x, float y) {
    u64 r; asm("mov.b64 %0, {%1, %2};" : "=l"(r) : "f"(x), "f"(y)); return r;
}
__device__ __forceinline__ void upk(u64 a, float& x, float& y) {
    asm("mov.b64 {%0, %1}, %2;" : "=f"(x), "=f"(y) : "l"(a));
}
__device__ __forceinline__ u64 fma2_(u64 a, u64 b, u64 c) {
    u64 d; asm("fma.rn.f32x2 %0, %1, %2, %3;" : "=l"(d) : "l"(a), "l"(b), "l"(c)); return d;
}
__device__ __forceinline__ u64 add2_(u64 a, u64 b) {
    u64 d; asm("add.rn.f32x2 %0, %1, %2;" : "=l"(d) : "l"(a), "l"(b)); return d;
}
__device__ __forceinline__ u64 sub2_(u64 a, u64 b) {
    u64 d; asm("sub.rn.f32x2 %0, %1, %2;" : "=l"(d) : "l"(a), "l"(b)); return d;
}

// ---------------- tf32 helpers ----------------
__device__ __forceinline__ u32 cvt_tf32(float x) {           // setup only
    u32 r; asm("cvt.rna.tf32.f32 %0, %1;" : "=r"(r) : "f"(x)); return r;
}
__device__ __forceinline__ u32 as_u32(float x) { return __float_as_uint(x); }

// accumulate: D = A*B + D
__device__ __forceinline__ void mma8(float* c, u32 a0, u32 a1, u32 a2, u32 a3,
                                     u32 b0, u32 b1) {
    asm("mma.sync.aligned.m16n8k8.row.col.f32.tf32.tf32.f32 "
        "{%0,%1,%2,%3}, {%4,%5,%6,%7}, {%8,%9}, {%0,%1,%2,%3};"
        : "+f"(c[0]), "+f"(c[1]), "+f"(c[2]), "+f"(c[3])
        : "r"(a0), "r"(a1), "r"(a2), "r"(a3), "r"(b0), "r"(b1));
}
// init: D = A*B + C  (C = persistent regs, no per-step accumulator init movs)
__device__ __forceinline__ void mma8_init(float* d, u32 a0, u32 a1, u32 a2, u32 a3,
                                          u32 b0, u32 b1,
                                          float c0, float c1, float c2, float c3) {
    asm("mma.sync.aligned.m16n8k8.row.col.f32.tf32.tf32.f32 "
        "{%0,%1,%2,%3}, {%4,%5,%6,%7}, {%8,%9}, {%10,%11,%12,%13};"
        : "=f"(d[0]), "=f"(d[1]), "=f"(d[2]), "=f"(d[3])
        : "r"(a0), "r"(a1), "r"(a2), "r"(a3), "r"(b0), "r"(b1),
          "f"(c0), "f"(c1), "f"(c2), "f"(c3));
}
// K=4 init for the (xt8, xt9, t, 1) feature block: D = A*B + 0
__device__ __forceinline__ void mma4_init(float* d, u32 a0, u32 a1, u32 b0,
                                          float c0, float c1, float c2, float c3) {
    asm("mma.sync.aligned.m16n8k4.row.col.f32.tf32.tf32.f32 "
        "{%0,%1,%2,%3}, {%4,%5}, {%6}, {%7,%8,%9,%10};"
        : "=f"(d[0]), "=f"(d[1]), "=f"(d[2]), "=f"(d[3])
        : "r"(a0), "r"(a1), "r"(b0), "f"(c0), "f"(c1), "f"(c2), "f"(c3));
}

// per-(chain, d) SDE raw constants
__device__ __forceinline__ void prep_cd(const float* __restrict__ zm,
                                        const float* __restrict__ zlv,
                                        int bb, int l, int d,
                                        float& mu, float& sinv, float& ssd) {
    const float* zmr = zm  + ((size_t)bb * MAXLEN + l) * LATENT;
    const float* zvr = zlv + ((size_t)bb * MAXLEN + l) * LATENT;
    float zmc = zmr[d];
    float zmp = (l > 0) ? zmr[d - LATENT] : 0.f;
    mu = zmc - zmp;
    float av = (l > 0) ? zvr[d - LATENT] : 0.f;
    float bv = zvr[d];
    float mx = fmaxf(av, bv);
    float sg = mx + log1pf(expf(-fabsf(av - bv)));   // logaddexp
    float sstd = expf(0.5f * sg);
    sinv = 1.f / sg;
    ssd  = sstd * 0.1f;                              // sigma_std * sqrt(dt)
}

// One warp = 16 chains (same l). m16n8k8/k4 tf32 MMA, weights in register
// B-fragments, raw fp32 bits as MMA inputs. Folded SDE constants in SMEM
// (per-lane private; paired as 16B loads). err accumulators in SMEM.
// Accumulator inits are folded into non-destructive-C MMA forms.
__global__ void __launch_bounds__(32, 16)
vae_mma8_kernel(const float* __restrict__ zm,
                const float* __restrict__ zlv,
                const float* __restrict__ W1,
                const float* __restrict__ b1,
                const float* __restrict__ W2,
                const float* __restrict__ b2,
                const float* __restrict__ noise,
                float* __restrict__ out)
{
    __shared__ __align__(16) ulonglong2 sKa[4][32];  // (nsinv, musinv)
    __shared__ __align__(16) ulonglong2 sKb[4][32];  // (mudt, hv)
    __shared__ __align__(16) u64        sKc[4][32];  // ssd
    __shared__ __align__(16) u64        sE [4][32];  // err accumulators

    const int lane = threadIdx.x;
    const int r  = lane >> 2;
    const int gc = lane & 3;
    const int base = blockIdx.x * 16;
    const int l   = base >> 9;          // uniform per warp (16 | 512)
    const int bb0 = base & 511;
    const int cA  = bb0 + r;
    const int cB  = bb0 + r + 8;

    // hidden-unit permutation: B-col n (=r) -> j_local
    const int jl = (r & 1) ? (r >> 1) + 4 : (r >> 1);
    const int d8r = 8 + (r & 1);        // nt1 col n=r -> latent d8 (even) / d9 (odd)

    // ---- static weight fragments (single tf32) ----
    u32 B1h0[8][2];                   // layer1 kt0 (features 0-7)
    u32 B1h1[8];                      // layer1 k4 block (features 8-11)
    u32 B2h[8][2][2];                 // layer2 [jt][nt][reg]

#pragma unroll
    for (int jt = 0; jt < 8; jt++) {
        int j = 8 * jt + jl;
        B1h0[jt][0] = cvt_tf32(W1[gc * HID + j]);
        B1h0[jt][1] = cvt_tf32(W1[(gc + 4) * HID + j]);
        float wt = (gc == 3) ? b1[j] : W1[(8 + gc) * HID + j];
        B1h1[jt] = cvt_tf32(wt);
        B2h[jt][0][0] = cvt_tf32(W2[(8 * jt + gc) * LATENT + jl]);
        B2h[jt][0][1] = cvt_tf32(W2[(8 * jt + gc + 4) * LATENT + jl]);
        B2h[jt][1][0] = cvt_tf32(W2[(8 * jt + gc) * LATENT + d8r]);
        B2h[jt][1][1] = cvt_tf32(W2[(8 * jt + gc + 4) * LATENT + d8r]);
    }

    // ---- SDE state: xt in regs; folded constants + err in SMEM ----
    u64 xt[2][2];
#pragma unroll
    for (int h = 0; h < 2; h++) {
        int bb = (h == 0) ? cA : cB;
        // nt0: d = (gc, gc+4)
        {
            float m0, s0, w0, m1, s1, w1;
            prep_cd(zm, zlv, bb, l, gc,     m0, s0, w0);
            prep_cd(zm, zlv, bb, l, gc + 4, m1, s1, w1);
            sKa[0 * 2 + h][lane] = make_ulonglong2(pk(-s0, -s1), pk(m0 * s0, m1 * s1));
            sKb[0 * 2 + h][lane] = make_ulonglong2(pk(m0 * DTC, m1 * DTC),
                                                   pk(0.5f * w0 * w0, 0.5f * w1 * w1));
            sKc[0 * 2 + h][lane] = pk(w0, w1);
            xt[0][h] = pk(m0, m1);
        }
        // nt1: d = (8, 9), redundant on ALL lanes
        {
            float m0, s0, w0, m1, s1, w1;
            prep_cd(zm, zlv, bb, l, 8, m0, s0, w0);
            prep_cd(zm, zlv, bb, l, 9, m1, s1, w1);
            sKa[1 * 2 + h][lane] = make_ulonglong2(pk(-s0, -s1), pk(m0 * s0, m1 * s1));
            sKb[1 * 2 + h][lane] = make_ulonglong2(pk(m0 * DTC, m1 * DTC),
                                                   pk(0.5f * w0 * w0, 0.5f * w1 * w1));
            sKc[1 * 2 + h][lane] = pk(w0, w1);
            xt[1][h] = pk(m0, m1);
        }
        sE[0 * 2 + h][lane] = 0ULL;
        sE[1 * 2 + h][lane] = 0ULL;
    }

    // bias values in S C-layout (persistent regs, consumed by mma8_init)
    const float bs0 = b2[gc];
    const float bs1 = b2[gc + 4];
    const float b28 = b2[8];
    const float b29 = b2[9];

    const float* nzp = noise + ((size_t)l * NSTEPS * BATCH + cA) * LATENT;
    const int nzstep = BATCH * LATENT;

#pragma unroll 1
    for (int s = 0; s < NSTEPS; s++) {
        const float tt = (float)(l + s) * DTC;

        // ---- noise gathers ----
        const float* nA = nzp;
        const float* nB = nzp + 8 * LATENT;
        u64 nzv[2][2];
        nzv[0][0] = pk(nA[gc], nA[gc + 4]);
        nzv[0][1] = pk(nB[gc], nB[gc + 4]);
        nzv[1][0] = *(const u64*)(nA + 8);    // (d8,d9), 8B-aligned
        nzv[1][1] = *(const u64*)(nB + 8);
        nzp += nzstep;

        // ---- A fragments (raw fp32 bits) ----
        float x0, x1, y0, y1;
        upk(xt[0][0], x0, x1);
        upk(xt[0][1], y0, y1);
        u32 A0 = as_u32(x0);
        u32 A1 = as_u32(y0);
        u32 A2 = as_u32(x1);
        u32 A3 = as_u32(y1);

        float fA8, fA9, fB8, fB9;
        upk(xt[1][0], fA8, fA9);
        upk(xt[1][1], fB8, fB9);
        float f0 = (gc == 0) ? fA8 : (gc == 1) ? fA9 : (gc == 2) ? tt : 1.0f;
        float f1 = (gc == 0) ? fB8 : (gc == 1) ? fB9 : (gc == 2) ? tt : 1.0f;
        u32 E0 = as_u32(f0);
        u32 E1 = as_u32(f1);

        // ---- MLP: layer-2 accumulators, 4 chains (nt x jt-parity) ----
        float S[2][2][4];

#pragma unroll
        for (int jt = 0; jt < 8; jt++) {
            float C[4];
            // C = E*W1[k4 block] + 0 ; then C += A*W1[kt0]
            mma4_init(C, E0, E1, B1h1[jt], 0.f, 0.f, 0.f, 0.f);
            mma8(C, A0, A1, A2, A3, B1h0[jt][0], B1h0[jt][1]);

            // relu + C->A fragment permute (c0,c2,c1,c3), raw bits
            u32 H0 = as_u32(fmaxf(C[0], 0.f));
            u32 H1 = as_u32(fmaxf(C[2], 0.f));
            u32 H2 = as_u32(fmaxf(C[1], 0.f));
            u32 H3 = as_u32(fmaxf(C[3], 0.f));

            if (jt == 0) {
                mma8_init(S[0][0], H0, H1, H2, H3, B2h[0][0][0], B2h[0][0][1],
                          bs0, bs1, bs0, bs1);
                mma8_init(S[1][0], H0, H1, H2, H3, B2h[0][1][0], B2h[0][1][1],
                          b28, b29, b28, b29);
            } else if (jt == 1) {
                mma8_init(S[0][1], H0, H1, H2, H3, B2h[1][0][0], B2h[1][0][1],
                          0.f, 0.f, 0.f, 0.f);
                mma8_init(S[1][1], H0, H1, H2, H3, B2h[1][1][0], B2h[1][1][1],
                          0.f, 0.f, 0.f, 0.f);
            } else {
                const int par = jt & 1;
                mma8(S[0][par], H0, H1, H2, H3, B2h[jt][0][0], B2h[jt][0][1]);
                mma8(S[1][par], H0, H1, H2, H3, B2h[jt][1][0], B2h[jt][1][1]);
            }
        }

        // ---- SDE update + score error ----
#pragma unroll
        for (int nt = 0; nt < 2; nt++) {
            u64 scp[2];
            scp[0] = pk(S[nt][0][0] + S[nt][1][0], S[nt][0][1] + S[nt][1][1]);
            scp[1] = pk(S[nt][0][2] + S[nt][1][2], S[nt][0][3] + S[nt][1][3]);
#pragma unroll
            for (int h = 0; h < 2; h++) {
                const int g = nt * 2 + h;
                ulonglong2 ka = sKa[g][lane];     // (nsinv, musinv)
                ulonglong2 kb = sKb[g][lane];     // (mudt, hv)
                u64 ssd      = sKc[g][lane];
                u64 logdx = fma2_(xt[nt][h], ka.x, ka.y);      // (mu-xt)*sinv
                u64 diff  = sub2_(logdx, scp[h]);
                u64 e     = sE[g][lane];
                sE[g][lane] = fma2_(diff, diff, e);
                u64 x = add2_(xt[nt][h], kb.x);                // + mu*dt
                x = fma2_(scp[h], kb.y, x);                    // + 0.5*var*dt*score
                xt[nt][h] = fma2_(nzv[nt][h], ssd, x);         // + ssd*dW
            }
        }
    }

    // ---- outputs (scatter from fragment layout) ----
    const float inv_n = 1.0f / (float)NSTEPS;
#pragma unroll
    for (int h = 0; h < 2; h++) {
        int bb = (h == 0) ? cA : cB;
        float* oS = out + ((size_t)bb * MAXLEN + l) * LATENT;
        float* oE = oS + (size_t)BATCH * MAXLEN * LATENT;
        float a, b;
        upk(xt[0][h], a, b);
        oS[gc]     = a;
        oS[gc + 4] = b;
        upk(sE[0 * 2 + h][lane], a, b);
        oE[gc]     = a * inv_n;
        oE[gc + 4] = b * inv_n;
        if (gc == 0) {
            upk(xt[1][h], a, b);
            *(float2*)(oS + 8) = make_float2(a, b);
            upk(sE[1 * 2 + h][lane], a, b);
            *(float2*)(oE + 8) = make_float2(a * inv_n, b * inv_n);
        }
    }
}

extern "C" void kernel_launch(void* const* d_in, const int* in_sizes, int n_in,
                              void* d_out, int out_size)
{
    const float* zm    = (const float*)d_in[0];  // [512,80,10]
    const float* zlv   = (const float*)d_in[1];  // [512,80,10]
    const float* W1    = (const float*)d_in[2];  // [11,64]
    const float* b1    = (const float*)d_in[3];  // [64]
    const float* W2    = (const float*)d_in[4];  // [64,10]
    const float* b2    = (const float*)d_in[5];  // [10]
    const float* noise = (const float*)d_in[6];  // [80,100,512,10]
    float* out = (float*)d_out;                  // [2,512,80,10]

    const int nblocks = BATCH * MAXLEN / 16;     // 2560 warps, 16 chains each
    vae_mma8_kernel<<<nblocks, 32>>>(zm, zlv, W1, b1, W2, b2, noise, out);
}